// round 1
// baseline (speedup 1.0000x reference)
#include <cuda_runtime.h>
#include <math.h>

#define NTOK 4096
#define HID  1024
#define FFN  2816
#define NEXP 8
#define NSLOT (NTOK * 2)

// ---------------- scratch (__device__ globals; no runtime allocation) ----------------
__device__ int   d_cnt[NEXP];
__device__ int   d_off[NEXP];
__device__ int   d_tok_expert[NSLOT];
__device__ float d_tok_w[NSLOT];
__device__ int   d_tok_pos[NSLOT];
__device__ int   d_slot_token[NSLOT];
__device__ float d_slot_w[NSLOT];
__device__ float d_H[(size_t)NSLOT * FFN];   // 8192 x 2816 fp32 = 92.3 MB

// ---------------- kernel 0: zero expert counters ----------------
__global__ void zero_cnt_kernel() {
    if (threadIdx.x < NEXP) d_cnt[threadIdx.x] = 0;
}

// ---------------- kernel 0b: zero output ----------------
__global__ void zero_out_kernel(float* out) {
    int i = blockIdx.x * blockDim.x + threadIdx.x;
    if (i < NTOK * HID) out[i] = 0.f;
}

// ---------------- kernel 1: gating (one block of 128 threads per token) ----------------
__global__ void gate_kernel(const float* __restrict__ x, const float* __restrict__ gw) {
    int t = blockIdx.x;
    int tid = threadIdx.x;                 // 128 threads
    const float* xr = x + (size_t)t * HID;

    float part[NEXP];
#pragma unroll
    for (int e = 0; e < NEXP; e++) part[e] = 0.f;

#pragma unroll
    for (int i = 0; i < HID / 128; i++) {
        float xv = xr[tid + i * 128];
#pragma unroll
        for (int e = 0; e < NEXP; e++)
            part[e] += xv * gw[e * HID + tid + i * 128];
    }

    __shared__ float sh[4][NEXP];
    int lane = tid & 31, w = tid >> 5;
#pragma unroll
    for (int e = 0; e < NEXP; e++) {
        float v = part[e];
        for (int s = 16; s > 0; s >>= 1) v += __shfl_down_sync(0xffffffffu, v, s);
        if (lane == 0) sh[w][e] = v;
    }
    __syncthreads();

    if (tid == 0) {
        float logit[NEXP];
#pragma unroll
        for (int e = 0; e < NEXP; e++)
            logit[e] = sh[0][e] + sh[1][e] + sh[2][e] + sh[3][e];

        // top-2 (first index wins ties, matching jax top_k)
        int i0 = 0;
        for (int e = 1; e < NEXP; e++) if (logit[e] > logit[i0]) i0 = e;
        int i1 = -1;
        for (int e = 0; e < NEXP; e++) {
            if (e == i0) continue;
            if (i1 < 0 || logit[e] > logit[i1]) i1 = e;
        }
        // renormalized top-2 softmax weights == 2-way softmax over the two logits
        float p1 = expf(logit[i1] - logit[i0]);
        float inv = 1.f / (1.f + p1);
        float w0 = inv, w1 = p1 * inv;

        int q0 = atomicAdd(&d_cnt[i0], 1);
        int q1 = atomicAdd(&d_cnt[i1], 1);
        d_tok_expert[t * 2 + 0] = i0;  d_tok_expert[t * 2 + 1] = i1;
        d_tok_w[t * 2 + 0]      = w0;  d_tok_w[t * 2 + 1]      = w1;
        d_tok_pos[t * 2 + 0]    = q0;  d_tok_pos[t * 2 + 1]    = q1;
    }
}

// ---------------- kernel 2: tiny exclusive scan ----------------
__global__ void scan_kernel() {
    if (threadIdx.x == 0) {
        int s = 0;
        for (int e = 0; e < NEXP; e++) { d_off[e] = s; s += d_cnt[e]; }
    }
}

// ---------------- kernel 3: scatter into compact per-expert slot lists ----------------
__global__ void scatter_kernel() {
    int idx = blockIdx.x * blockDim.x + threadIdx.x;
    if (idx < NSLOT) {
        int e = d_tok_expert[idx];
        int slot = d_off[e] + d_tok_pos[idx];
        d_slot_token[slot] = idx >> 1;
        d_slot_w[slot] = d_tok_w[idx];
    }
}

// ---------------- GEMM tile config ----------------
#define BM 128
#define BN 64
#define BK 16
#define PADA 4
#define PADB 4

// ---------------- kernel 4: grouped GEMM1 (fused w1/w3 + SwiGLU) ----------------
// H[slot, o] = silu(x[t] . w1[e,o]) * (x[t] . w3[e,o])
__global__ void __launch_bounds__(256, 1)
gemm1_kernel(const float* __restrict__ x,
             const float* __restrict__ w1,
             const float* __restrict__ w3) {
    int e = blockIdx.z;
    int cnt = d_cnt[e];
    int off = d_off[e];
    int m0 = blockIdx.y * BM;
    if (m0 >= cnt) return;
    int n0 = blockIdx.x * BN;

    __shared__ float As[BK][BM + PADA];
    __shared__ float B1s[BK][BN + PADB];
    __shared__ float B3s[BK][BN + PADB];

    int tid = threadIdx.x;
    int tx = tid & 15;        // n direction (4 cols each)
    int ty = tid >> 4;        // m direction (8 rows each)

    // A loader: 2 rows per thread (rowA, rowA+64), float4 along k
    int rowA = tid >> 2;          // 0..63
    int kq = (tid & 3) * 4;       // 0,4,8,12
    int mA0 = m0 + rowA;       if (mA0 >= cnt) mA0 = cnt - 1;
    int mA1 = m0 + rowA + 64;  if (mA1 >= cnt) mA1 = cnt - 1;
    const float* xa0 = x + (size_t)d_slot_token[off + mA0] * HID + kq;
    const float* xa1 = x + (size_t)d_slot_token[off + mA1] * HID + kq;

    // B loader: row oB of w1/w3 for this expert
    int oB = n0 + (tid >> 2);     // 0..63 within tile
    const float* b1p = w1 + ((size_t)e * FFN + oB) * HID + kq;
    const float* b3p = w3 + ((size_t)e * FFN + oB) * HID + kq;

    float acc1[8][4], acc3[8][4];
#pragma unroll
    for (int i = 0; i < 8; i++)
#pragma unroll
        for (int j = 0; j < 4; j++) { acc1[i][j] = 0.f; acc3[i][j] = 0.f; }

    for (int k0 = 0; k0 < HID; k0 += BK) {
        float4 va0 = *(const float4*)(xa0 + k0);
        float4 va1 = *(const float4*)(xa1 + k0);
        float4 vb1 = *(const float4*)(b1p + k0);
        float4 vb3 = *(const float4*)(b3p + k0);

        As[kq + 0][rowA] = va0.x; As[kq + 1][rowA] = va0.y;
        As[kq + 2][rowA] = va0.z; As[kq + 3][rowA] = va0.w;
        As[kq + 0][rowA + 64] = va1.x; As[kq + 1][rowA + 64] = va1.y;
        As[kq + 2][rowA + 64] = va1.z; As[kq + 3][rowA + 64] = va1.w;

        int nb = oB - n0;
        B1s[kq + 0][nb] = vb1.x; B1s[kq + 1][nb] = vb1.y;
        B1s[kq + 2][nb] = vb1.z; B1s[kq + 3][nb] = vb1.w;
        B3s[kq + 0][nb] = vb3.x; B3s[kq + 1][nb] = vb3.y;
        B3s[kq + 2][nb] = vb3.z; B3s[kq + 3][nb] = vb3.w;

        __syncthreads();

#pragma unroll
        for (int kk = 0; kk < BK; kk++) {
            float4 a0 = *(const float4*)&As[kk][ty * 8];
            float4 a1 = *(const float4*)&As[kk][ty * 8 + 4];
            float4 bb1 = *(const float4*)&B1s[kk][tx * 4];
            float4 bb3 = *(const float4*)&B3s[kk][tx * 4];
            float a[8] = {a0.x, a0.y, a0.z, a0.w, a1.x, a1.y, a1.z, a1.w};
            float b1v[4] = {bb1.x, bb1.y, bb1.z, bb1.w};
            float b3v[4] = {bb3.x, bb3.y, bb3.z, bb3.w};
#pragma unroll
            for (int i = 0; i < 8; i++)
#pragma unroll
                for (int j = 0; j < 4; j++) {
                    acc1[i][j] += a[i] * b1v[j];
                    acc3[i][j] += a[i] * b3v[j];
                }
        }
        __syncthreads();
    }

    // epilogue: SwiGLU, vector store
#pragma unroll
    for (int i = 0; i < 8; i++) {
        int m = m0 + ty * 8 + i;
        if (m < cnt) {
            float4 hv;
            float r[4];
#pragma unroll
            for (int j = 0; j < 4; j++) {
                float s = acc1[i][j];
                r[j] = (s / (1.f + expf(-s))) * acc3[i][j];
            }
            hv.x = r[0]; hv.y = r[1]; hv.z = r[2]; hv.w = r[3];
            *(float4*)&d_H[(size_t)(off + m) * FFN + n0 + tx * 4] = hv;
        }
    }
}

// ---------------- kernel 5: grouped GEMM2 (H . w2^T, weighted atomic accumulate) ----------------
__global__ void __launch_bounds__(256, 1)
gemm2_kernel(const float* __restrict__ w2, float* __restrict__ out) {
    int e = blockIdx.z;
    int cnt = d_cnt[e];
    int off = d_off[e];
    int m0 = blockIdx.y * BM;
    if (m0 >= cnt) return;
    int n0 = blockIdx.x * BN;

    __shared__ float As[BK][BM + PADA];
    __shared__ float Bs[BK][BN + PADB];

    int tid = threadIdx.x;
    int tx = tid & 15;
    int ty = tid >> 4;

    int rowA = tid >> 2;
    int kq = (tid & 3) * 4;
    int mA0 = m0 + rowA;       if (mA0 >= cnt) mA0 = cnt - 1;
    int mA1 = m0 + rowA + 64;  if (mA1 >= cnt) mA1 = cnt - 1;
    const float* ha0 = d_H + (size_t)(off + mA0) * FFN + kq;
    const float* ha1 = d_H + (size_t)(off + mA1) * FFN + kq;

    int nB = n0 + (tid >> 2);
    const float* bp = w2 + ((size_t)e * HID + nB) * FFN + kq;

    float acc[8][4];
#pragma unroll
    for (int i = 0; i < 8; i++)
#pragma unroll
        for (int j = 0; j < 4; j++) acc[i][j] = 0.f;

    for (int k0 = 0; k0 < FFN; k0 += BK) {
        float4 va0 = *(const float4*)(ha0 + k0);
        float4 va1 = *(const float4*)(ha1 + k0);
        float4 vb  = *(const float4*)(bp + k0);

        As[kq + 0][rowA] = va0.x; As[kq + 1][rowA] = va0.y;
        As[kq + 2][rowA] = va0.z; As[kq + 3][rowA] = va0.w;
        As[kq + 0][rowA + 64] = va1.x; As[kq + 1][rowA + 64] = va1.y;
        As[kq + 2][rowA + 64] = va1.z; As[kq + 3][rowA + 64] = va1.w;

        int nb = nB - n0;
        Bs[kq + 0][nb] = vb.x; Bs[kq + 1][nb] = vb.y;
        Bs[kq + 2][nb] = vb.z; Bs[kq + 3][nb] = vb.w;

        __syncthreads();

#pragma unroll
        for (int kk = 0; kk < BK; kk++) {
            float4 a0 = *(const float4*)&As[kk][ty * 8];
            float4 a1 = *(const float4*)&As[kk][ty * 8 + 4];
            float4 bb = *(const float4*)&Bs[kk][tx * 4];
            float a[8] = {a0.x, a0.y, a0.z, a0.w, a1.x, a1.y, a1.z, a1.w};
            float bv[4] = {bb.x, bb.y, bb.z, bb.w};
#pragma unroll
            for (int i = 0; i < 8; i++)
#pragma unroll
                for (int j = 0; j < 4; j++)
                    acc[i][j] += a[i] * bv[j];
        }
        __syncthreads();
    }

#pragma unroll
    for (int i = 0; i < 8; i++) {
        int m = m0 + ty * 8 + i;
        if (m < cnt) {
            int t = d_slot_token[off + m];
            float wgt = d_slot_w[off + m];
            float* orow = out + (size_t)t * HID + n0 + tx * 4;
#pragma unroll
            for (int j = 0; j < 4; j++)
                atomicAdd(&orow[j], wgt * acc[i][j]);
        }
    }
}

// ---------------- launch ----------------
extern "C" void kernel_launch(void* const* d_in, const int* in_sizes, int n_in,
                              void* d_out, int out_size) {
    const float* x  = (const float*)d_in[0];
    const float* gw = (const float*)d_in[1];
    const float* w1 = (const float*)d_in[2];
    const float* w2 = (const float*)d_in[3];
    const float* w3 = (const float*)d_in[4];
    float* out = (float*)d_out;

    zero_cnt_kernel<<<1, 32>>>();
    zero_out_kernel<<<(NTOK * HID + 255) / 256, 256>>>(out);
    gate_kernel<<<NTOK, 128>>>(x, gw);
    scan_kernel<<<1, 1>>>();
    scatter_kernel<<<(NSLOT + 255) / 256, 256>>>();

    dim3 g1(FFN / BN, (NTOK + BM - 1) / BM, NEXP);   // 44 x 32 x 8
    gemm1_kernel<<<g1, 256>>>(x, w1, w3);

    dim3 g2(HID / BN, (NTOK + BM - 1) / BM, NEXP);   // 16 x 32 x 8
    gemm2_kernel<<<g2, 256>>>(w2, out);
}

// round 3
// speedup vs baseline: 2.5417x; 2.5417x over previous
#include <cuda_runtime.h>
#include <math.h>
#include <stdint.h>

#define NTOK 4096
#define HID  1024
#define FFN  2816
#define NEXP 8
#define NSLOT (NTOK * 2)

// ================= helpers =================
__device__ __forceinline__ uint32_t smem_u32(const void* p) {
    uint32_t a;
    asm("{ .reg .u64 t; cvta.to.shared.u64 t, %1; cvt.u32.u64 %0, t; }" : "=r"(a) : "l"(p));
    return a;
}

#define CP_ASYNC16(dst_u32, src_ptr) \
    asm volatile("cp.async.cg.shared.global [%0], [%1], 16;" :: "r"(dst_u32), "l"(src_ptr))
#define CP_COMMIT() asm volatile("cp.async.commit_group;")
#define CP_WAIT(n)  asm volatile("cp.async.wait_group %0;" :: "n"(n))

__device__ __forceinline__ uint32_t f2tf32(float f) {
    uint32_t r; asm("cvt.rna.tf32.f32 %0, %1;" : "=r"(r) : "f"(f)); return r;
}

__device__ __forceinline__ void mma_tf32(float c[4],
                                         uint32_t a0, uint32_t a1, uint32_t a2, uint32_t a3,
                                         uint32_t b0, uint32_t b1) {
    asm volatile("mma.sync.aligned.m16n8k8.row.col.f32.tf32.tf32.f32 "
        "{%0,%1,%2,%3}, {%4,%5,%6,%7}, {%8,%9}, {%0,%1,%2,%3};"
        : "+f"(c[0]), "+f"(c[1]), "+f"(c[2]), "+f"(c[3])
        : "r"(a0), "r"(a1), "r"(a2), "r"(a3), "r"(b0), "r"(b1));
}

// ================= scratch =================
__device__ int   d_cnt[NEXP];
__device__ int   d_off[NEXP];
__device__ int   d_tok_expert[NSLOT];
__device__ float d_tok_w[NSLOT];
__device__ int   d_tok_pos[NSLOT];
__device__ int   d_slot_token[NSLOT];
__device__ float d_slot_w[NSLOT];
__device__ float d_H[(size_t)NSLOT * FFN];   // 92.3 MB

// ================= small kernels =================
__global__ void zero_cnt_kernel() { if (threadIdx.x < NEXP) d_cnt[threadIdx.x] = 0; }

__global__ void zero_out_kernel(float* out) {
    int i = blockIdx.x * blockDim.x + threadIdx.x;
    if (i < NTOK * HID) out[i] = 0.f;
}

__global__ void gate_kernel(const float* __restrict__ x, const float* __restrict__ gw) {
    int t = blockIdx.x;
    int tid = threadIdx.x;  // 128
    const float* xr = x + (size_t)t * HID;
    float part[NEXP];
#pragma unroll
    for (int e = 0; e < NEXP; e++) part[e] = 0.f;
#pragma unroll
    for (int i = 0; i < HID / 128; i++) {
        float xv = xr[tid + i * 128];
#pragma unroll
        for (int e = 0; e < NEXP; e++) part[e] += xv * gw[e * HID + tid + i * 128];
    }
    __shared__ float sh[4][NEXP];
    int lane = tid & 31, w = tid >> 5;
#pragma unroll
    for (int e = 0; e < NEXP; e++) {
        float v = part[e];
        for (int s = 16; s > 0; s >>= 1) v += __shfl_down_sync(0xffffffffu, v, s);
        if (lane == 0) sh[w][e] = v;
    }
    __syncthreads();
    if (tid == 0) {
        float logit[NEXP];
#pragma unroll
        for (int e = 0; e < NEXP; e++) logit[e] = sh[0][e] + sh[1][e] + sh[2][e] + sh[3][e];
        int i0 = 0;
        for (int e = 1; e < NEXP; e++) if (logit[e] > logit[i0]) i0 = e;
        int i1 = -1;
        for (int e = 0; e < NEXP; e++) {
            if (e == i0) continue;
            if (i1 < 0 || logit[e] > logit[i1]) i1 = e;
        }
        float p1 = expf(logit[i1] - logit[i0]);
        float inv = 1.f / (1.f + p1);
        int q0 = atomicAdd(&d_cnt[i0], 1);
        int q1 = atomicAdd(&d_cnt[i1], 1);
        d_tok_expert[t * 2 + 0] = i0;  d_tok_expert[t * 2 + 1] = i1;
        d_tok_w[t * 2 + 0] = inv;      d_tok_w[t * 2 + 1] = p1 * inv;
        d_tok_pos[t * 2 + 0] = q0;     d_tok_pos[t * 2 + 1] = q1;
    }
}

__global__ void scan_kernel() {
    if (threadIdx.x == 0) {
        int s = 0;
        for (int e = 0; e < NEXP; e++) { d_off[e] = s; s += d_cnt[e]; }
    }
}

__global__ void scatter_kernel() {
    int idx = blockIdx.x * blockDim.x + threadIdx.x;
    if (idx < NSLOT) {
        int e = d_tok_expert[idx];
        int slot = d_off[e] + d_tok_pos[idx];
        d_slot_token[slot] = idx >> 1;
        d_slot_w[slot] = d_tok_w[idx];
    }
}

// ================= tensor GEMMs (mma.sync tf32) =================
// CTA tile 256(M) x 64(N), BK=32. 8 warps: 4(m) x 2(n); warp tile 64x32.
// SMEM pitch 36 floats -> conflict-free fragment LDS (bank = (4g+t) perm).

#define PA 36
#define G1_ABUF (256 * PA)          // floats / stage
#define G1_BBUF (128 * PA)          // w1(64 rows) + w3(64 rows)
#define G2_BBUF (64 * PA)

__global__ void __launch_bounds__(256)
gemm1_tc(const float* __restrict__ x,
         const float* __restrict__ w1,
         const float* __restrict__ w3) {
    int e = blockIdx.z;
    int cnt = d_cnt[e], off = d_off[e];
    int m0 = blockIdx.y * 256;
    if (m0 >= cnt) return;
    int n0 = blockIdx.x * 64;

    extern __shared__ float sm_[];
    float* As = sm_;                    // 2 x G1_ABUF
    float* Bs = sm_ + 2 * G1_ABUF;      // 2 x G1_BBUF
    __shared__ int s_tok[256];

    int tid = threadIdx.x;
    int wid = tid >> 5, lane = tid & 31;
    int g = lane >> 2, t = lane & 3;
    int wm = (wid >> 1) * 64, wn = (wid & 1) * 32;

    {
        int m = m0 + tid; if (m >= cnt) m = cnt - 1;
        s_tok[tid] = d_slot_token[off + m];
    }
    __syncthreads();

    // ---- loader setup ----
    uint32_t As_u = smem_u32(As), Bs_u = smem_u32(Bs);
    int lq = tid & 7;                 // float4 slot within 32-float row
    int lr = tid >> 3;                // 0..31
    const float* asrc[8]; uint32_t adst[8];
#pragma unroll
    for (int i = 0; i < 8; i++) {
        int row = lr + i * 32;
        asrc[i] = x + (size_t)s_tok[row] * HID + lq * 4;
        adst[i] = As_u + (uint32_t)(row * PA + lq * 4) * 4u;
    }
    const float* bsrc[4]; uint32_t bdst[4];
#pragma unroll
    for (int i = 0; i < 4; i++) {
        int row = lr + i * 32;        // 0..127
        const float* w = (row < 64)
            ? (w1 + ((size_t)e * FFN + n0 + row) * HID)
            : (w3 + ((size_t)e * FFN + n0 + row - 64) * HID);
        bsrc[i] = w + lq * 4;
        bdst[i] = Bs_u + (uint32_t)(row * PA + lq * 4) * 4u;
    }

#define G1_LOAD(c_, buf_) do { \
    int _k = (c_) * 32; \
    uint32_t _ao = (buf_) * (G1_ABUF * 4u); \
    uint32_t _bo = (buf_) * (G1_BBUF * 4u); \
    _Pragma("unroll") for (int _i = 0; _i < 8; _i++) CP_ASYNC16(adst[_i] + _ao, asrc[_i] + _k); \
    _Pragma("unroll") for (int _i = 0; _i < 4; _i++) CP_ASYNC16(bdst[_i] + _bo, bsrc[_i] + _k); \
} while (0)

    float acc1[4][4][4], acc3[4][4][4];
#pragma unroll
    for (int i = 0; i < 4; i++)
#pragma unroll
        for (int j = 0; j < 4; j++)
#pragma unroll
            for (int k = 0; k < 4; k++) { acc1[i][j][k] = 0.f; acc3[i][j][k] = 0.f; }

    const int NC = HID / 32;   // 32
    G1_LOAD(0, 0); CP_COMMIT();

    for (int c = 0; c < NC; c++) {
        if (c + 1 < NC) { G1_LOAD(c + 1, (c + 1) & 1); CP_COMMIT(); CP_WAIT(1); }
        else            { CP_WAIT(0); }
        __syncthreads();

        const float* A = As + (c & 1) * G1_ABUF;
        const float* B = Bs + (c & 1) * G1_BBUF;
#pragma unroll
        for (int ks = 0; ks < 4; ks++) {
            uint32_t a[4][4];
#pragma unroll
            for (int i = 0; i < 4; i++) {
                const float* pa = A + (wm + i * 16 + g) * PA + ks * 8 + t;
                a[i][0] = f2tf32(pa[0]);
                a[i][1] = f2tf32(pa[8 * PA]);
                a[i][2] = f2tf32(pa[4]);
                a[i][3] = f2tf32(pa[8 * PA + 4]);
            }
#pragma unroll
            for (int j = 0; j < 4; j++) {
                const float* pb1 = B + (wn + j * 8 + g) * PA + ks * 8 + t;
                const float* pb3 = pb1 + 64 * PA;
                uint32_t b10 = f2tf32(pb1[0]), b11 = f2tf32(pb1[4]);
                uint32_t b30 = f2tf32(pb3[0]), b31 = f2tf32(pb3[4]);
#pragma unroll
                for (int i = 0; i < 4; i++) {
                    mma_tf32(acc1[i][j], a[i][0], a[i][1], a[i][2], a[i][3], b10, b11);
                    mma_tf32(acc3[i][j], a[i][0], a[i][1], a[i][2], a[i][3], b30, b31);
                }
            }
        }
        __syncthreads();
    }

    // ---- epilogue: SwiGLU -> d_H (float2 stores) ----
#pragma unroll
    for (int i = 0; i < 4; i++) {
#pragma unroll
        for (int hh = 0; hh < 2; hh++) {
            int m = m0 + wm + i * 16 + g + hh * 8;
            if (m < cnt) {
                float* hrow = d_H + (size_t)(off + m) * FFN + n0 + wn;
#pragma unroll
                for (int j = 0; j < 4; j++) {
                    float s1a = acc1[i][j][hh * 2 + 0], s1b = acc1[i][j][hh * 2 + 1];
                    float v3a = acc3[i][j][hh * 2 + 0], v3b = acc3[i][j][hh * 2 + 1];
                    float2 hv;
                    hv.x = (s1a / (1.f + expf(-s1a))) * v3a;
                    hv.y = (s1b / (1.f + expf(-s1b))) * v3b;
                    *(float2*)(hrow + j * 8 + 2 * t) = hv;
                }
            }
        }
    }
}

__global__ void __launch_bounds__(256)
gemm2_tc(const float* __restrict__ w2, float* __restrict__ out) {
    int e = blockIdx.z;
    int cnt = d_cnt[e], off = d_off[e];
    int m0 = blockIdx.y * 256;
    if (m0 >= cnt) return;
    int n0 = blockIdx.x * 64;

    extern __shared__ float sm_[];
    float* As = sm_;
    float* Bs = sm_ + 2 * G1_ABUF;

    int tid = threadIdx.x;
    int wid = tid >> 5, lane = tid & 31;
    int g = lane >> 2, t = lane & 3;
    int wm = (wid >> 1) * 64, wn = (wid & 1) * 32;

    uint32_t As_u = smem_u32(As), Bs_u = smem_u32(Bs);
    int lq = tid & 7;
    int lr = tid >> 3;
    const float* asrc[8]; uint32_t adst[8];
#pragma unroll
    for (int i = 0; i < 8; i++) {
        int row = lr + i * 32;
        int m = m0 + row; if (m >= cnt) m = cnt - 1;
        asrc[i] = d_H + (size_t)(off + m) * FFN + lq * 4;
        adst[i] = As_u + (uint32_t)(row * PA + lq * 4) * 4u;
    }
    const float* bsrc[2]; uint32_t bdst[2];
#pragma unroll
    for (int i = 0; i < 2; i++) {
        int row = lr + i * 32;        // 0..63
        bsrc[i] = w2 + ((size_t)e * HID + n0 + row) * FFN + lq * 4;
        bdst[i] = Bs_u + (uint32_t)(row * PA + lq * 4) * 4u;
    }

#define G2_LOAD(c_, buf_) do { \
    int _k = (c_) * 32; \
    uint32_t _ao = (buf_) * (G1_ABUF * 4u); \
    uint32_t _bo = (buf_) * (G2_BBUF * 4u); \
    _Pragma("unroll") for (int _i = 0; _i < 8; _i++) CP_ASYNC16(adst[_i] + _ao, asrc[_i] + _k); \
    _Pragma("unroll") for (int _i = 0; _i < 2; _i++) CP_ASYNC16(bdst[_i] + _bo, bsrc[_i] + _k); \
} while (0)

    float acc[4][4][4];
#pragma unroll
    for (int i = 0; i < 4; i++)
#pragma unroll
        for (int j = 0; j < 4; j++)
#pragma unroll
            for (int k = 0; k < 4; k++) acc[i][j][k] = 0.f;

    const int NC = FFN / 32;   // 88
    G2_LOAD(0, 0); CP_COMMIT();

    for (int c = 0; c < NC; c++) {
        if (c + 1 < NC) { G2_LOAD(c + 1, (c + 1) & 1); CP_COMMIT(); CP_WAIT(1); }
        else            { CP_WAIT(0); }
        __syncthreads();

        const float* A = As + (c & 1) * G1_ABUF;
        const float* B = Bs + (c & 1) * G2_BBUF;
#pragma unroll
        for (int ks = 0; ks < 4; ks++) {
            uint32_t a[4][4];
#pragma unroll
            for (int i = 0; i < 4; i++) {
                const float* pa = A + (wm + i * 16 + g) * PA + ks * 8 + t;
                a[i][0] = f2tf32(pa[0]);
                a[i][1] = f2tf32(pa[8 * PA]);
                a[i][2] = f2tf32(pa[4]);
                a[i][3] = f2tf32(pa[8 * PA + 4]);
            }
#pragma unroll
            for (int j = 0; j < 4; j++) {
                const float* pb = B + (wn + j * 8 + g) * PA + ks * 8 + t;
                uint32_t b0 = f2tf32(pb[0]), b1 = f2tf32(pb[4]);
#pragma unroll
                for (int i = 0; i < 4; i++)
                    mma_tf32(acc[i][j], a[i][0], a[i][1], a[i][2], a[i][3], b0, b1);
            }
        }
        __syncthreads();
    }

    // ---- epilogue: weighted atomic accumulate ----
#pragma unroll
    for (int i = 0; i < 4; i++) {
#pragma unroll
        for (int hh = 0; hh < 2; hh++) {
            int m = m0 + wm + i * 16 + g + hh * 8;
            if (m < cnt) {
                int tok = d_slot_token[off + m];
                float wgt = d_slot_w[off + m];
                float* orow = out + (size_t)tok * HID + n0 + wn;
#pragma unroll
                for (int j = 0; j < 4; j++) {
                    atomicAdd(&orow[j * 8 + 2 * t],     wgt * acc[i][j][hh * 2 + 0]);
                    atomicAdd(&orow[j * 8 + 2 * t + 1], wgt * acc[i][j][hh * 2 + 1]);
                }
            }
        }
    }
}

// ================= launch =================
extern "C" void kernel_launch(void* const* d_in, const int* in_sizes, int n_in,
                              void* d_out, int out_size) {
    const float* x  = (const float*)d_in[0];
    const float* gw = (const float*)d_in[1];
    const float* w1 = (const float*)d_in[2];
    const float* w2 = (const float*)d_in[3];
    const float* w3 = (const float*)d_in[4];
    float* out = (float*)d_out;

    const int smem1 = (2 * G1_ABUF + 2 * G1_BBUF) * 4;   // 110592 B
    const int smem2 = (2 * G1_ABUF + 2 * G2_BBUF) * 4;   //  92160 B
    cudaFuncSetAttribute(gemm1_tc, cudaFuncAttributeMaxDynamicSharedMemorySize, smem1);
    cudaFuncSetAttribute(gemm2_tc, cudaFuncAttributeMaxDynamicSharedMemorySize, smem2);

    zero_cnt_kernel<<<1, 32>>>();
    zero_out_kernel<<<(NTOK * HID + 255) / 256, 256>>>(out);
    gate_kernel<<<NTOK, 128>>>(x, gw);
    scan_kernel<<<1, 1>>>();
    scatter_kernel<<<(NSLOT + 255) / 256, 256>>>();

    dim3 g1(FFN / 64, NTOK / 256, NEXP);   // 44 x 16 x 8
    gemm1_tc<<<g1, 256, smem1>>>(x, w1, w3);

    dim3 g2(HID / 64, NTOK / 256, NEXP);   // 16 x 16 x 8
    gemm2_tc<<<g2, 256, smem2>>>(w2, out);
}